// round 16
// baseline (speedup 1.0000x reference)
#include <cuda_runtime.h>
#include <cuda_bf16.h>
#include <cstdint>

#define DD 128
#define NMAX 50000
#define EMAX 600000
#define GMAX 64

// ---------------- scratch (no allocations allowed) ----------------
__device__ float g_agg[NMAX * DD];
__device__ float g_h[NMAX * DD];
__device__ float g_x[NMAX * DD];
__device__ float g_pool[GMAX * DD + GMAX];   // sums then counts (one memset)
__device__ __nv_bfloat16 g_wT1_hi[3 * DD * DD];
__device__ __nv_bfloat16 g_wT1_lo[3 * DD * DD];
__device__ __nv_bfloat16 g_wTc_hi[3 * DD * 256];
__device__ __nv_bfloat16 g_wTc_lo[3 * DD * 256];
__device__ float g_bc[3 * DD];
__device__ int g_deg[NMAX];
__device__ int g_rowptr[NMAX + 1];
__device__ int g_cursor[NMAX];
__device__ int g_adj[EMAX];
__device__ int g_bsum[128];

// ---------------- helpers ----------------
__device__ __forceinline__ uint32_t smem_u32(const void* p) {
    uint32_t a;
    asm("{ .reg .u64 t; cvta.to.shared.u64 t, %1; cvt.u32.u64 %0, t; }"
        : "=r"(a) : "l"(p));
    return a;
}
__device__ __forceinline__ uint32_t packbf(float a, float b) {
    __nv_bfloat162 t = __floats2bfloat162_rn(a, b);
    return *reinterpret_cast<uint32_t*>(&t);
}
__device__ __forceinline__ void ldm4(uint32_t& r0, uint32_t& r1, uint32_t& r2,
                                     uint32_t& r3, uint32_t addr) {
    asm volatile("ldmatrix.sync.aligned.m8n8.x4.shared.b16 {%0,%1,%2,%3}, [%4];"
                 : "=r"(r0), "=r"(r1), "=r"(r2), "=r"(r3) : "r"(addr));
}
__device__ __forceinline__ void mma16816(float* c, const uint32_t* a, const uint32_t* b) {
    asm volatile(
        "mma.sync.aligned.m16n8k16.row.col.f32.bf16.bf16.f32 "
        "{%0,%1,%2,%3}, {%4,%5,%6,%7}, {%8,%9}, {%0,%1,%2,%3};"
        : "+f"(c[0]), "+f"(c[1]), "+f"(c[2]), "+f"(c[3])
        : "r"(a[0]), "r"(a[1]), "r"(a[2]), "r"(a[3]), "r"(b[0]), "r"(b[1]));
}
__device__ __forceinline__ void cp16(uint32_t saddr, const void* g) {
    asm volatile("cp.async.ca.shared.global [%0], [%1], 16;" :: "r"(saddr), "l"(g));
}
#define CP_COMMIT() asm volatile("cp.async.commit_group;" ::: "memory")
#define CP_WAIT0() asm volatile("cp.async.wait_group 0;" ::: "memory")

// ---------------- CSR build ----------------
__global__ void deg_kernel(const int* __restrict__ ei, int* __restrict__ deg, int E) {
    int e = blockIdx.x * blockDim.x + threadIdx.x;
    if (e < E) atomicAdd(&deg[ei[E + e]], 1);
}
__global__ void scan1(const int* __restrict__ deg, int* __restrict__ rowptr,
                      int* __restrict__ bsum, int N) {
    __shared__ int ws[16];
    int i = blockIdx.x * 512 + threadIdx.x;
    int lane = threadIdx.x & 31, w = threadIdx.x >> 5;
    int v = (i < N) ? deg[i] : 0;
#pragma unroll
    for (int o = 1; o < 32; o <<= 1) {
        int t = __shfl_up_sync(0xFFFFFFFFu, v, o);
        if (lane >= o) v += t;
    }
    if (lane == 31) ws[w] = v;
    __syncthreads();
    if (w == 0) {
        int s = (lane < 16) ? ws[lane] : 0;
#pragma unroll
        for (int o = 1; o < 16; o <<= 1) {
            int t = __shfl_up_sync(0xFFFFFFFFu, s, o);
            if (lane >= o) s += t;
        }
        if (lane < 16) ws[lane] = s;
    }
    __syncthreads();
    if (w > 0) v += ws[w - 1];
    if (i < N) rowptr[i + 1] = v;
    if (threadIdx.x == 511) bsum[blockIdx.x] = v;
}
__global__ void scan2(int* __restrict__ bsum, int nb) {
    if (threadIdx.x == 0) {
        int run = 0;
        for (int b = 0; b < nb; b++) { int t = bsum[b]; bsum[b] = run; run += t; }
    }
}
// finalizes rowptr AND writes cursor (merged)
__global__ void scan3(int* __restrict__ rowptr, const int* __restrict__ bsum,
                      int* __restrict__ cursor, int N) {
    int i = blockIdx.x * blockDim.x + threadIdx.x;
    if (i == 0) {
        rowptr[0] = 0;
        cursor[0] = 0;
    } else if (i <= N) {
        int v = rowptr[i] + bsum[(i - 1) >> 9];
        rowptr[i] = v;
        if (i < N) cursor[i] = v;
    }
}
__global__ void fill_adj(const int* __restrict__ ei, int* __restrict__ cursor,
                         int* __restrict__ adj, int E) {
    int e = blockIdx.x * blockDim.x + threadIdx.x;
    if (e < E) adj[atomicAdd(&cursor[ei[E + e]], 1)] = ei[e];
}

// ---------------- gather: xa[i] = x[i] + sum_{j in N(i)} x[j] ----------------
__global__ void gather_kernel(const float* __restrict__ x,
                              const int* __restrict__ rowptr,
                              const int* __restrict__ adj,
                              float* __restrict__ xa, int N) {
    int node = (blockIdx.x * blockDim.x + threadIdx.x) >> 5;
    int lane = threadIdx.x & 31;
    if (node >= N) return;
    float4 acc = *(const float4*)(x + (size_t)node * DD + lane * 4);
    int e = rowptr[node], end = rowptr[node + 1];
    for (; e + 1 < end; e += 2) {
        int s0 = adj[e], s1 = adj[e + 1];
        float4 v0 = *(const float4*)(x + (size_t)s0 * DD + lane * 4);
        float4 v1 = *(const float4*)(x + (size_t)s1 * DD + lane * 4);
        acc.x += v0.x + v1.x; acc.y += v0.y + v1.y;
        acc.z += v0.z + v1.z; acc.w += v0.w + v1.w;
    }
    if (e < end) {
        int s = adj[e];
        float4 v = *(const float4*)(x + (size_t)s * DD + lane * 4);
        acc.x += v.x; acc.y += v.y; acc.z += v.z; acc.w += v.w;
    }
    *(float4*)(xa + (size_t)node * DD + lane * 4) = acc;
}

// ---------------- weight prep ----------------
__global__ void prep_weights(const float* __restrict__ w1, const float* __restrict__ w2,
                             const float* __restrict__ rw, const float* __restrict__ b2,
                             const float* __restrict__ rb,
                             __nv_bfloat16* __restrict__ wT1h, __nv_bfloat16* __restrict__ wT1l,
                             __nv_bfloat16* __restrict__ wTch, __nv_bfloat16* __restrict__ wTcl,
                             float* __restrict__ bc) {
    int idx = blockIdx.x * blockDim.x + threadIdx.x;
    if (idx < 3 * DD * DD) {
        int l = idx / (DD * DD), r = idx % (DD * DD), n = r / DD, k = r % DD;
        float v = w1[l * DD * DD + k * DD + n];
        __nv_bfloat16 hi = __float2bfloat16_rn(v);
        wT1h[idx] = hi;
        wT1l[idx] = __float2bfloat16_rn(v - __bfloat162float(hi));
    }
    int i2 = idx - 3 * DD * DD;
    if (i2 >= 0 && i2 < 3 * DD * 256) {
        int l = i2 / (DD * 256), r = i2 % (DD * 256), n = r / 256, k2 = r % 256;
        float v = (k2 < DD) ? w2[l * DD * DD + k2 * DD + n]
                            : rw[l * DD * DD + (k2 - DD) * DD + n];
        __nv_bfloat16 hi = __float2bfloat16_rn(v);
        wTch[i2] = hi;
        wTcl[i2] = __float2bfloat16_rn(v - __bfloat162float(hi));
    }
    if (idx < 3 * DD) bc[idx] = b2[idx] + rb[idx];
}

// ---------------- bf16x3 GEMM, 64x128 CTA tile (finer waves) ----------------
// CAT=false: C = relu_if(A @ W^T + bias)          W^T: [128n x 128k]
// CAT=true : C = relu_if([A | A2] @ W^T + bias)   W^T: [128n x 256k]
// 256 thr, 8 warps in 2m x 4n grid, warp tile 32x32. Non-persistent: 1 tile/CTA.
// smem: A hi@0 (9216) lo@9216 + B hi@18432 lo@36864 = 55296 -> 2+ CTA/SM.
#define TROW 72
#define O_AH 0u
#define O_AL 9216u
#define O_BH 18432u
#define O_BL 36864u
#define SM_TOTAL 55296

template <bool CAT>
__global__ __launch_bounds__(256, 2) void gemm_bf16(
    const float* __restrict__ A, const float* __restrict__ A2,
    const __nv_bfloat16* __restrict__ Bhi, const __nv_bfloat16* __restrict__ Blo,
    const float* __restrict__ bias, float* __restrict__ C, int M, int relu) {
    extern __shared__ char smem[];
    const uint32_t sb = smem_u32(smem);
    const int tid = threadIdx.x, wid = tid >> 5, lane = tid & 31;
    const int wm = wid & 1, wn = wid >> 1;       // 2m x 4n
    const int BK = CAT ? 256 : 128;
    const int NC = CAT ? 4 : 2;
    const int m0 = blockIdx.x * 64;

    const uint32_t aBase = (uint32_t)((wm * 32 + (lane & 15)) * TROW + (lane >> 4) * 8) * 2;
    const uint32_t bBase = (uint32_t)((wn * 32 + (lane & 7) + ((lane >> 4) & 1) * 8) * TROW +
                                      ((lane >> 3) & 1) * 8) * 2;

    float acc[2][4][4];
#pragma unroll
    for (int mi = 0; mi < 2; mi++)
#pragma unroll
        for (int ni = 0; ni < 4; ni++)
#pragma unroll
            for (int q = 0; q < 4; q++) acc[mi][ni][q] = 0.f;

    for (int c = 0; c < NC; c++) {
        // ---- fill B chunk c via cp.async (128 n-rows x 64 k) ----
        const int bk0 = c * 64;
#pragma unroll
        for (int it = 0; it < 4; it++) {
            int i = tid + it * 256;
            int row = i >> 3, s = i & 7;
            uint32_t off = (uint32_t)(row * TROW * 2 + s * 16);
            cp16(sb + O_BH + off, Bhi + (size_t)row * BK + bk0 + s * 8);
            cp16(sb + O_BL + off, Blo + (size_t)row * BK + bk0 + s * 8);
        }
        CP_COMMIT();
        // ---- fill A chunk c (64 rows x 64 k; LDG + bf16 split) ----
        const float* Asrc = CAT ? ((c < 2) ? A : A2) : A;
        const int ak0 = CAT ? ((c & 1) * 64) : (c * 64);
#pragma unroll
        for (int it = 0; it < 4; it++) {
            int i = tid + it * 256;
            int row = i >> 4, s = i & 15;
            int m = m0 + row;
            float4 v = (m < M) ? *(const float4*)(Asrc + (size_t)m * DD + ak0 + s * 4)
                               : make_float4(0.f, 0.f, 0.f, 0.f);
            float hx = __bfloat162float(__float2bfloat16_rn(v.x));
            float hy = __bfloat162float(__float2bfloat16_rn(v.y));
            float hz = __bfloat162float(__float2bfloat16_rn(v.z));
            float hw = __bfloat162float(__float2bfloat16_rn(v.w));
            uint32_t off = (uint32_t)(row * TROW * 2 + s * 8);
            *(uint2*)(smem + O_AH + off) = make_uint2(packbf(hx, hy), packbf(hz, hw));
            *(uint2*)(smem + O_AL + off) =
                make_uint2(packbf(v.x - hx, v.y - hy), packbf(v.z - hz, v.w - hw));
        }
        CP_WAIT0();
        __syncthreads();

        // ---- compute chunk c ----
#pragma unroll
        for (int ks = 0; ks < 4; ks++) {
            uint32_t ah[2][4], al[2][4];
#pragma unroll
            for (int mi = 0; mi < 2; mi++) {
                uint32_t ao = aBase + (uint32_t)(mi * 16 * TROW * 2 + ks * 32);
                ldm4(ah[mi][0], ah[mi][1], ah[mi][2], ah[mi][3], sb + O_AH + ao);
                ldm4(al[mi][0], al[mi][1], al[mi][2], al[mi][3], sb + O_AL + ao);
            }
            uint32_t bh[4][2], bl[4][2];
#pragma unroll
            for (int np = 0; np < 2; np++) {
                uint32_t bo = bBase + (uint32_t)(np * 16 * TROW * 2 + ks * 32);
                ldm4(bh[2 * np][0], bh[2 * np][1], bh[2 * np + 1][0], bh[2 * np + 1][1],
                     sb + O_BH + bo);
                ldm4(bl[2 * np][0], bl[2 * np][1], bl[2 * np + 1][0], bl[2 * np + 1][1],
                     sb + O_BL + bo);
            }
#pragma unroll
            for (int mi = 0; mi < 2; mi++)
#pragma unroll
                for (int ni = 0; ni < 4; ni++) {
                    mma16816(acc[mi][ni], ah[mi], bh[ni]);
                    mma16816(acc[mi][ni], ah[mi], bl[ni]);
                    mma16816(acc[mi][ni], al[mi], bh[ni]);
                }
        }
        __syncthreads();
    }

    // ---- epilogue ----
    const int tq = lane >> 2, tr = lane & 3;
#pragma unroll
    for (int mi = 0; mi < 2; mi++) {
        int r0 = m0 + wm * 32 + mi * 16 + tq;
        int r1 = r0 + 8;
#pragma unroll
        for (int ni = 0; ni < 4; ni++) {
            int col = wn * 32 + ni * 8 + tr * 2;
            float b0 = bias[col], b1 = bias[col + 1];
            float2 v0 = make_float2(acc[mi][ni][0] + b0, acc[mi][ni][1] + b1);
            float2 v1 = make_float2(acc[mi][ni][2] + b0, acc[mi][ni][3] + b1);
            if (relu) {
                v0.x = fmaxf(v0.x, 0.f); v0.y = fmaxf(v0.y, 0.f);
                v1.x = fmaxf(v1.x, 0.f); v1.y = fmaxf(v1.y, 0.f);
            }
            if (r0 < M) *(float2*)(C + (size_t)r0 * DD + col) = v0;
            if (r1 < M) *(float2*)(C + (size_t)r1 * DD + col) = v1;
        }
    }
}

// ---------------- pooling ----------------
__global__ void pool_accum(const float* __restrict__ x,
                           const int* __restrict__ batch,
                           float* __restrict__ sums, float* __restrict__ counts,
                           int N) {
    int d = threadIdx.x;
    int per = (N + gridDim.x - 1) / gridDim.x;
    int n0 = blockIdx.x * per;
    int n1 = min(N, n0 + per);
    if (n0 >= n1) return;
    int cur = batch[n0];
    float acc = 0.f;
    int cnt = 0;
    for (int n = n0; n < n1; n++) {
        int g = batch[n];
        if (g != cur) {
            atomicAdd(&sums[cur * DD + d], acc);
            if (d == 0) atomicAdd(&counts[cur], (float)cnt);
            acc = 0.f; cnt = 0; cur = g;
        }
        acc += x[(size_t)n * DD + d];
        cnt++;
    }
    atomicAdd(&sums[cur * DD + d], acc);
    if (d == 0) atomicAdd(&counts[cur], (float)cnt);
}

__global__ void final_out(const float* __restrict__ sums,
                          const float* __restrict__ counts,
                          const float* __restrict__ out_w,
                          const float* __restrict__ out_b,
                          float* __restrict__ out) {
    int g = blockIdx.x;
    int d = threadIdx.x;
    float c = fmaxf(counts[g], 1.f);
    float v = (sums[g * DD + d] / c) * out_w[d];
    __shared__ float red[4];
#pragma unroll
    for (int o = 16; o; o >>= 1) v += __shfl_down_sync(0xFFFFFFFFu, v, o);
    if ((d & 31) == 0) red[d >> 5] = v;
    __syncthreads();
    if (d == 0) out[g] = red[0] + red[1] + red[2] + red[3] + out_b[0];
}

// ---------------- launch ----------------
extern "C" void kernel_launch(void* const* d_in, const int* in_sizes, int n_in,
                              void* d_out, int out_size) {
    const float* x_in = (const float*)d_in[0];
    const int* ei = (const int*)d_in[1];
    const int* batch = (const int*)d_in[2];
    const float* w1 = (const float*)d_in[3];
    const float* b1 = (const float*)d_in[4];
    const float* w2 = (const float*)d_in[5];
    const float* b2 = (const float*)d_in[6];
    const float* rw = (const float*)d_in[7];
    const float* rb = (const float*)d_in[8];
    const float* ow = (const float*)d_in[9];
    const float* ob = (const float*)d_in[10];
    float* out = (float*)d_out;

    int N = in_sizes[0] / DD;   // 50000
    int E = in_sizes[1] / 2;    // 600000
    int G = out_size;           // 64

    float *xa, *h, *xb, *pool, *bc;
    __nv_bfloat16 *wT1h, *wT1l, *wTch, *wTcl;
    int *deg, *rowptr, *cursor, *adj, *bsum;
    cudaGetSymbolAddress((void**)&xa, g_agg);
    cudaGetSymbolAddress((void**)&h, g_h);
    cudaGetSymbolAddress((void**)&xb, g_x);
    cudaGetSymbolAddress((void**)&pool, g_pool);
    cudaGetSymbolAddress((void**)&wT1h, g_wT1_hi);
    cudaGetSymbolAddress((void**)&wT1l, g_wT1_lo);
    cudaGetSymbolAddress((void**)&wTch, g_wTc_hi);
    cudaGetSymbolAddress((void**)&wTcl, g_wTc_lo);
    cudaGetSymbolAddress((void**)&bc, g_bc);
    cudaGetSymbolAddress((void**)&deg, g_deg);
    cudaGetSymbolAddress((void**)&rowptr, g_rowptr);
    cudaGetSymbolAddress((void**)&cursor, g_cursor);
    cudaGetSymbolAddress((void**)&adj, g_adj);
    cudaGetSymbolAddress((void**)&bsum, g_bsum);
    float* sums = pool;
    float* counts = pool + (size_t)G * DD;

    cudaFuncSetAttribute(gemm_bf16<false>, cudaFuncAttributeMaxDynamicSharedMemorySize, SM_TOTAL);
    cudaFuncSetAttribute(gemm_bf16<true>, cudaFuncAttributeMaxDynamicSharedMemorySize, SM_TOTAL);

    int nb = (N + 511) / 512;
    int gemm_blocks = (N + 63) / 64;   // 782 tiles, 1 tile per CTA

    // ---- CSR build ----
    cudaMemsetAsync(deg, 0, (size_t)N * sizeof(int), 0);
    deg_kernel<<<(E + 255) / 256, 256>>>(ei, deg, E);
    scan1<<<nb, 512>>>(deg, rowptr, bsum, N);
    scan2<<<1, 32>>>(bsum, nb);
    scan3<<<(N + 256) / 256, 256>>>(rowptr, bsum, cursor, N);
    fill_adj<<<(E + 255) / 256, 256>>>(ei, cursor, adj, E);

    prep_weights<<<(3 * DD * DD + 3 * DD * 256 + 255) / 256, 256>>>(
        w1, w2, rw, b2, rb, wT1h, wT1l, wTch, wTcl, bc);

    int gather_blocks = (N * 32 + 255) / 256;
    const float* xp = x_in;
    for (int i = 0; i < 3; i++) {
        gather_kernel<<<gather_blocks, 256>>>(xp, rowptr, adj, xa, N);
        gemm_bf16<false><<<gemm_blocks, 256, SM_TOTAL>>>(
            xa, nullptr, wT1h + (size_t)i * DD * DD, wT1l + (size_t)i * DD * DD,
            b1 + i * DD, h, N, 1);
        gemm_bf16<true><<<gemm_blocks, 256, SM_TOTAL>>>(
            h, xp, wTch + (size_t)i * DD * 256, wTcl + (size_t)i * DD * 256,
            bc + i * DD, xb, N, (i < 2) ? 1 : 0);
        xp = xb;
    }

    cudaMemsetAsync(pool, 0, ((size_t)G * DD + G) * sizeof(float), 0);
    pool_accum<<<256, DD>>>(xp, batch, sums, counts, N);
    final_out<<<G, DD>>>(sums, counts, ow, ob, out);
}

// round 17
// speedup vs baseline: 1.0818x; 1.0818x over previous
#include <cuda_runtime.h>
#include <cuda_bf16.h>
#include <cstdint>

#define DD 128
#define NMAX 50000
#define EMAX 600000
#define GMAX 64

// ---------------- scratch (no allocations allowed) ----------------
__device__ float g_agg[NMAX * DD];
__device__ float g_h[NMAX * DD];
__device__ float g_x[NMAX * DD];
__device__ float g_pool[GMAX * DD + GMAX];   // sums then counts (one memset)
__device__ __nv_bfloat16 g_wT1_hi[3 * DD * DD];
__device__ __nv_bfloat16 g_wT1_lo[3 * DD * DD];
__device__ __nv_bfloat16 g_wTc_hi[3 * DD * 256];
__device__ __nv_bfloat16 g_wTc_lo[3 * DD * 256];
__device__ float g_bc[3 * DD];
__device__ int g_deg[NMAX];
__device__ int g_rowptr[NMAX + 1];
__device__ int g_cursor[NMAX];
__device__ int g_adj[EMAX];
__device__ int g_bsum[128];

// ---------------- helpers ----------------
__device__ __forceinline__ uint32_t smem_u32(const void* p) {
    uint32_t a;
    asm("{ .reg .u64 t; cvta.to.shared.u64 t, %1; cvt.u32.u64 %0, t; }"
        : "=r"(a) : "l"(p));
    return a;
}
__device__ __forceinline__ uint32_t packbf(float a, float b) {
    __nv_bfloat162 t = __floats2bfloat162_rn(a, b);
    return *reinterpret_cast<uint32_t*>(&t);
}
__device__ __forceinline__ void ldm4(uint32_t& r0, uint32_t& r1, uint32_t& r2,
                                     uint32_t& r3, uint32_t addr) {
    asm volatile("ldmatrix.sync.aligned.m8n8.x4.shared.b16 {%0,%1,%2,%3}, [%4];"
                 : "=r"(r0), "=r"(r1), "=r"(r2), "=r"(r3) : "r"(addr));
}
__device__ __forceinline__ void mma16816(float* c, const uint32_t* a, const uint32_t* b) {
    asm volatile(
        "mma.sync.aligned.m16n8k16.row.col.f32.bf16.bf16.f32 "
        "{%0,%1,%2,%3}, {%4,%5,%6,%7}, {%8,%9}, {%0,%1,%2,%3};"
        : "+f"(c[0]), "+f"(c[1]), "+f"(c[2]), "+f"(c[3])
        : "r"(a[0]), "r"(a[1]), "r"(a[2]), "r"(a[3]), "r"(b[0]), "r"(b[1]));
}
__device__ __forceinline__ void cp16(uint32_t saddr, const void* g) {
    asm volatile("cp.async.ca.shared.global [%0], [%1], 16;" :: "r"(saddr), "l"(g));
}
#define CP_COMMIT() asm volatile("cp.async.commit_group;" ::: "memory")
#define CP_WAIT0() asm volatile("cp.async.wait_group 0;" ::: "memory")

// ---------------- CSR build ----------------
__global__ void deg_kernel(const int* __restrict__ ei, int* __restrict__ deg, int E) {
    int e = blockIdx.x * blockDim.x + threadIdx.x;
    if (e < E) atomicAdd(&deg[ei[E + e]], 1);
}
__global__ void scan1(const int* __restrict__ deg, int* __restrict__ rowptr,
                      int* __restrict__ bsum, int N) {
    __shared__ int ws[16];
    int i = blockIdx.x * 512 + threadIdx.x;
    int lane = threadIdx.x & 31, w = threadIdx.x >> 5;
    int v = (i < N) ? deg[i] : 0;
#pragma unroll
    for (int o = 1; o < 32; o <<= 1) {
        int t = __shfl_up_sync(0xFFFFFFFFu, v, o);
        if (lane >= o) v += t;
    }
    if (lane == 31) ws[w] = v;
    __syncthreads();
    if (w == 0) {
        int s = (lane < 16) ? ws[lane] : 0;
#pragma unroll
        for (int o = 1; o < 16; o <<= 1) {
            int t = __shfl_up_sync(0xFFFFFFFFu, s, o);
            if (lane >= o) s += t;
        }
        if (lane < 16) ws[lane] = s;
    }
    __syncthreads();
    if (w > 0) v += ws[w - 1];
    if (i < N) rowptr[i + 1] = v;
    if (threadIdx.x == 511) bsum[blockIdx.x] = v;
}
// finalizes rowptr AND writes cursor; computes needed bsum prefixes inline
// (block b needs at most 2 distinct prefixes: one warp each, strided reduce)
__global__ void scan3(int* __restrict__ rowptr, const int* __restrict__ bsum,
                      int* __restrict__ cursor, int N) {
    __shared__ int pref[2];
    const int base = blockIdx.x * 256;
    const int tid = threadIdx.x;
    const int w = tid >> 5, lane = tid & 31;
    const int jA = (base <= 1) ? 0 : ((base - 1) >> 9);
    const int jB = (base + 254) >> 9;
    if (w < 2) {
        int j = (w == 0) ? jA : jB;
        int s = 0;
        for (int b = lane; b < j; b += 32) s += bsum[b];
#pragma unroll
        for (int o = 16; o; o >>= 1) s += __shfl_down_sync(0xFFFFFFFFu, s, o);
        if (lane == 0) pref[w] = s;
    }
    __syncthreads();
    int i = base + tid;
    if (i == 0) {
        rowptr[0] = 0;
        cursor[0] = 0;
    } else if (i <= N) {
        int j = (i - 1) >> 9;
        int v = rowptr[i] + ((j == jA) ? pref[0] : pref[1]);
        rowptr[i] = v;
        if (i < N) cursor[i] = v;
    }
}
__global__ void fill_adj(const int* __restrict__ ei, int* __restrict__ cursor,
                         int* __restrict__ adj, int E) {
    int e = blockIdx.x * blockDim.x + threadIdx.x;
    if (e < E) adj[atomicAdd(&cursor[ei[E + e]], 1)] = ei[e];
}

// ---------------- gather: xa[i] = x[i] + sum_{j in N(i)} x[j] (4-way MLP) ----------
__global__ void gather_kernel(const float* __restrict__ x,
                              const int* __restrict__ rowptr,
                              const int* __restrict__ adj,
                              float* __restrict__ xa, int N) {
    int node = (blockIdx.x * blockDim.x + threadIdx.x) >> 5;
    int lane = threadIdx.x & 31;
    if (node >= N) return;
    float4 acc = *(const float4*)(x + (size_t)node * DD + lane * 4);
    int e = rowptr[node], end = rowptr[node + 1];
    for (; e + 3 < end; e += 4) {
        int s0 = adj[e], s1 = adj[e + 1], s2 = adj[e + 2], s3 = adj[e + 3];
        float4 v0 = *(const float4*)(x + (size_t)s0 * DD + lane * 4);
        float4 v1 = *(const float4*)(x + (size_t)s1 * DD + lane * 4);
        float4 v2 = *(const float4*)(x + (size_t)s2 * DD + lane * 4);
        float4 v3 = *(const float4*)(x + (size_t)s3 * DD + lane * 4);
        acc.x += (v0.x + v1.x) + (v2.x + v3.x);
        acc.y += (v0.y + v1.y) + (v2.y + v3.y);
        acc.z += (v0.z + v1.z) + (v2.z + v3.z);
        acc.w += (v0.w + v1.w) + (v2.w + v3.w);
    }
    for (; e < end; e++) {
        int s = adj[e];
        float4 v = *(const float4*)(x + (size_t)s * DD + lane * 4);
        acc.x += v.x; acc.y += v.y; acc.z += v.z; acc.w += v.w;
    }
    *(float4*)(xa + (size_t)node * DD + lane * 4) = acc;
}

// ---------------- weight prep ----------------
__global__ void prep_weights(const float* __restrict__ w1, const float* __restrict__ w2,
                             const float* __restrict__ rw, const float* __restrict__ b2,
                             const float* __restrict__ rb,
                             __nv_bfloat16* __restrict__ wT1h, __nv_bfloat16* __restrict__ wT1l,
                             __nv_bfloat16* __restrict__ wTch, __nv_bfloat16* __restrict__ wTcl,
                             float* __restrict__ bc) {
    int idx = blockIdx.x * blockDim.x + threadIdx.x;
    if (idx < 3 * DD * DD) {
        int l = idx / (DD * DD), r = idx % (DD * DD), n = r / DD, k = r % DD;
        float v = w1[l * DD * DD + k * DD + n];
        __nv_bfloat16 hi = __float2bfloat16_rn(v);
        wT1h[idx] = hi;
        wT1l[idx] = __float2bfloat16_rn(v - __bfloat162float(hi));
    }
    int i2 = idx - 3 * DD * DD;
    if (i2 >= 0 && i2 < 3 * DD * 256) {
        int l = i2 / (DD * 256), r = i2 % (DD * 256), n = r / 256, k2 = r % 256;
        float v = (k2 < DD) ? w2[l * DD * DD + k2 * DD + n]
                            : rw[l * DD * DD + (k2 - DD) * DD + n];
        __nv_bfloat16 hi = __float2bfloat16_rn(v);
        wTch[i2] = hi;
        wTcl[i2] = __float2bfloat16_rn(v - __bfloat162float(hi));
    }
    if (idx < 3 * DD) bc[idx] = b2[idx] + rb[idx];
}

// ---------------- persistent bf16x3 GEMM, 2 CTAs/SM, single-buffered (R15) --------
// CAT=false: C = relu_if(A @ W^T + bias)          W^T: [128n x 128k]
// CAT=true : C = relu_if([A | A2] @ W^T + bias)   W^T: [128n x 256k]
#define TROW 72
#define O_AH 0u
#define O_AL 18432u
#define O_BH 36864u
#define O_BL 55296u
#define SM_TOTAL 73728

template <bool CAT>
__global__ __launch_bounds__(256, 2) void gemm_bf16(
    const float* __restrict__ A, const float* __restrict__ A2,
    const __nv_bfloat16* __restrict__ Bhi, const __nv_bfloat16* __restrict__ Blo,
    const float* __restrict__ bias, float* __restrict__ C, int M, int relu) {
    extern __shared__ char smem[];
    const uint32_t sb = smem_u32(smem);
    const int tid = threadIdx.x, wid = tid >> 5, lane = tid & 31;
    const int wm = wid & 3, wn = wid >> 2;
    const int BK = CAT ? 256 : 128;
    const int NC = CAT ? 4 : 2;
    const int tiles = (M + 127) / 128;

    const uint32_t aBase = (uint32_t)((wm * 32 + (lane & 15)) * TROW + (lane >> 4) * 8) * 2;
    const uint32_t bBase = (uint32_t)((wn * 64 + (lane & 7) + ((lane >> 4) & 1) * 8) * TROW +
                                      ((lane >> 3) & 1) * 8) * 2;

    for (int t = blockIdx.x; t < tiles; t += gridDim.x) {
        const int m0 = t * 128;
        float acc[2][8][4];
#pragma unroll
        for (int mi = 0; mi < 2; mi++)
#pragma unroll
            for (int ni = 0; ni < 8; ni++)
#pragma unroll
                for (int q = 0; q < 4; q++) acc[mi][ni][q] = 0.f;

        for (int c = 0; c < NC; c++) {
            // ---- fill B chunk c via cp.async ----
            const int bk0 = c * 64;
#pragma unroll
            for (int it = 0; it < 4; it++) {
                int i = tid + it * 256;
                int row = i >> 3, s = i & 7;
                uint32_t off = (uint32_t)(row * TROW * 2 + s * 16);
                cp16(sb + O_BH + off, Bhi + (size_t)row * BK + bk0 + s * 8);
                cp16(sb + O_BL + off, Blo + (size_t)row * BK + bk0 + s * 8);
            }
            CP_COMMIT();
            // ---- fill A chunk c (LDG + bf16 split) ----
            const float* Asrc = CAT ? ((c < 2) ? A : A2) : A;
            const int ak0 = CAT ? ((c & 1) * 64) : (c * 64);
#pragma unroll
            for (int it = 0; it < 8; it++) {
                int i = tid + it * 256;
                int row = i >> 4, s = i & 15;
                int m = m0 + row;
                float4 v = (m < M) ? *(const float4*)(Asrc + (size_t)m * DD + ak0 + s * 4)
                                   : make_float4(0.f, 0.f, 0.f, 0.f);
                float hx = __bfloat162float(__float2bfloat16_rn(v.x));
                float hy = __bfloat162float(__float2bfloat16_rn(v.y));
                float hz = __bfloat162float(__float2bfloat16_rn(v.z));
                float hw = __bfloat162float(__float2bfloat16_rn(v.w));
                uint32_t off = (uint32_t)(row * TROW * 2 + s * 8);
                *(uint2*)(smem + O_AH + off) = make_uint2(packbf(hx, hy), packbf(hz, hw));
                *(uint2*)(smem + O_AL + off) =
                    make_uint2(packbf(v.x - hx, v.y - hy), packbf(v.z - hz, v.w - hw));
            }
            CP_WAIT0();
            __syncthreads();

            // ---- compute chunk c ----
#pragma unroll
            for (int ks = 0; ks < 4; ks++) {
                uint32_t ah[2][4], al[2][4];
#pragma unroll
                for (int mi = 0; mi < 2; mi++) {
                    uint32_t ao = aBase + (uint32_t)(mi * 16 * TROW * 2 + ks * 32);
                    ldm4(ah[mi][0], ah[mi][1], ah[mi][2], ah[mi][3], sb + O_AH + ao);
                    ldm4(al[mi][0], al[mi][1], al[mi][2], al[mi][3], sb + O_AL + ao);
                }
                uint32_t bh[8][2], bl[8][2];
#pragma unroll
                for (int np = 0; np < 4; np++) {
                    uint32_t bo = bBase + (uint32_t)(np * 16 * TROW * 2 + ks * 32);
                    ldm4(bh[2 * np][0], bh[2 * np][1], bh[2 * np + 1][0], bh[2 * np + 1][1],
                         sb + O_BH + bo);
                    ldm4(bl[2 * np][0], bl[2 * np][1], bl[2 * np + 1][0], bl[2 * np + 1][1],
                         sb + O_BL + bo);
                }
#pragma unroll
                for (int mi = 0; mi < 2; mi++)
#pragma unroll
                    for (int ni = 0; ni < 8; ni++) {
                        mma16816(acc[mi][ni], ah[mi], bh[ni]);
                        mma16816(acc[mi][ni], ah[mi], bl[ni]);
                        mma16816(acc[mi][ni], al[mi], bh[ni]);
                    }
            }
            __syncthreads();
        }

        // ---- epilogue (registers only) ----
        const int tq = lane >> 2, tr = lane & 3;
#pragma unroll
        for (int mi = 0; mi < 2; mi++) {
            int r0 = m0 + wm * 32 + mi * 16 + tq;
            int r1 = r0 + 8;
#pragma unroll
            for (int ni = 0; ni < 8; ni++) {
                int col = wn * 64 + ni * 8 + tr * 2;
                float b0 = bias[col], b1 = bias[col + 1];
                float2 v0 = make_float2(acc[mi][ni][0] + b0, acc[mi][ni][1] + b1);
                float2 v1 = make_float2(acc[mi][ni][2] + b0, acc[mi][ni][3] + b1);
                if (relu) {
                    v0.x = fmaxf(v0.x, 0.f); v0.y = fmaxf(v0.y, 0.f);
                    v1.x = fmaxf(v1.x, 0.f); v1.y = fmaxf(v1.y, 0.f);
                }
                if (r0 < M) *(float2*)(C + (size_t)r0 * DD + col) = v0;
                if (r1 < M) *(float2*)(C + (size_t)r1 * DD + col) = v1;
            }
        }
    }
}

// ---------------- pooling ----------------
__global__ void pool_accum(const float* __restrict__ x,
                           const int* __restrict__ batch,
                           float* __restrict__ sums, float* __restrict__ counts,
                           int N) {
    int d = threadIdx.x;
    int per = (N + gridDim.x - 1) / gridDim.x;
    int n0 = blockIdx.x * per;
    int n1 = min(N, n0 + per);
    if (n0 >= n1) return;
    int cur = batch[n0];
    float acc = 0.f;
    int cnt = 0;
    for (int n = n0; n < n1; n++) {
        int g = batch[n];
        if (g != cur) {
            atomicAdd(&sums[cur * DD + d], acc);
            if (d == 0) atomicAdd(&counts[cur], (float)cnt);
            acc = 0.f; cnt = 0; cur = g;
        }
        acc += x[(size_t)n * DD + d];
        cnt++;
    }
    atomicAdd(&sums[cur * DD + d], acc);
    if (d == 0) atomicAdd(&counts[cur], (float)cnt);
}

__global__ void final_out(const float* __restrict__ sums,
                          const float* __restrict__ counts,
                          const float* __restrict__ out_w,
                          const float* __restrict__ out_b,
                          float* __restrict__ out) {
    int g = blockIdx.x;
    int d = threadIdx.x;
    float c = fmaxf(counts[g], 1.f);
    float v = (sums[g * DD + d] / c) * out_w[d];
    __shared__ float red[4];
#pragma unroll
    for (int o = 16; o; o >>= 1) v += __shfl_down_sync(0xFFFFFFFFu, v, o);
    if ((d & 31) == 0) red[d >> 5] = v;
    __syncthreads();
    if (d == 0) out[g] = red[0] + red[1] + red[2] + red[3] + out_b[0];
}

// ---------------- launch ----------------
extern "C" void kernel_launch(void* const* d_in, const int* in_sizes, int n_in,
                              void* d_out, int out_size) {
    const float* x_in = (const float*)d_in[0];
    const int* ei = (const int*)d_in[1];
    const int* batch = (const int*)d_in[2];
    const float* w1 = (const float*)d_in[3];
    const float* b1 = (const float*)d_in[4];
    const float* w2 = (const float*)d_in[5];
    const float* b2 = (const float*)d_in[6];
    const float* rw = (const float*)d_in[7];
    const float* rb = (const float*)d_in[8];
    const float* ow = (const float*)d_in[9];
    const float* ob = (const float*)d_in[10];
    float* out = (float*)d_out;

    int N = in_sizes[0] / DD;   // 50000
    int E = in_sizes[1] / 2;    // 600000
    int G = out_size;           // 64

    float *xa, *h, *xb, *pool, *bc;
    __nv_bfloat16 *wT1h, *wT1l, *wTch, *wTcl;
    int *deg, *rowptr, *cursor, *adj, *bsum;
    cudaGetSymbolAddress((void**)&xa, g_agg);
    cudaGetSymbolAddress((void**)&h, g_h);
    cudaGetSymbolAddress((void**)&xb, g_x);
    cudaGetSymbolAddress((void**)&pool, g_pool);
    cudaGetSymbolAddress((void**)&wT1h, g_wT1_hi);
    cudaGetSymbolAddress((void**)&wT1l, g_wT1_lo);
    cudaGetSymbolAddress((void**)&wTch, g_wTc_hi);
    cudaGetSymbolAddress((void**)&wTcl, g_wTc_lo);
    cudaGetSymbolAddress((void**)&bc, g_bc);
    cudaGetSymbolAddress((void**)&deg, g_deg);
    cudaGetSymbolAddress((void**)&rowptr, g_rowptr);
    cudaGetSymbolAddress((void**)&cursor, g_cursor);
    cudaGetSymbolAddress((void**)&adj, g_adj);
    cudaGetSymbolAddress((void**)&bsum, g_bsum);
    float* sums = pool;
    float* counts = pool + (size_t)G * DD;

    cudaFuncSetAttribute(gemm_bf16<false>, cudaFuncAttributeMaxDynamicSharedMemorySize, SM_TOTAL);
    cudaFuncSetAttribute(gemm_bf16<true>, cudaFuncAttributeMaxDynamicSharedMemorySize, SM_TOTAL);

    int nb = (N + 511) / 512;
    const int GRID = 296;  // 2 CTAs per SM

    // ---- CSR build ----
    cudaMemsetAsync(deg, 0, (size_t)N * sizeof(int), 0);
    deg_kernel<<<(E + 255) / 256, 256>>>(ei, deg, E);
    scan1<<<nb, 512>>>(deg, rowptr, bsum, N);
    scan3<<<(N + 256) / 256, 256>>>(rowptr, bsum, cursor, N);
    fill_adj<<<(E + 255) / 256, 256>>>(ei, cursor, adj, E);

    prep_weights<<<(3 * DD * DD + 3 * DD * 256 + 255) / 256, 256>>>(
        w1, w2, rw, b2, rb, wT1h, wT1l, wTch, wTcl, bc);

    int gather_blocks = (N * 32 + 255) / 256;
    const float* xp = x_in;
    for (int i = 0; i < 3; i++) {
        gather_kernel<<<gather_blocks, 256>>>(xp, rowptr, adj, xa, N);
        gemm_bf16<false><<<GRID, 256, SM_TOTAL>>>(
            xa, nullptr, wT1h + (size_t)i * DD * DD, wT1l + (size_t)i * DD * DD,
            b1 + i * DD, h, N, 1);
        gemm_bf16<true><<<GRID, 256, SM_TOTAL>>>(
            h, xp, wTch + (size_t)i * DD * 256, wTcl + (size_t)i * DD * 256,
            bc + i * DD, xb, N, (i < 2) ? 1 : 0);
        xp = xb;
    }

    cudaMemsetAsync(pool, 0, ((size_t)G * DD + G) * sizeof(float), 0);
    pool_accum<<<256, DD>>>(xp, batch, sums, counts, N);
    final_out<<<G, DD>>>(sums, counts, ow, ob, out);
}